// round 1
// baseline (speedup 1.0000x reference)
#include <cuda_runtime.h>

static constexpr int B = 256;
static constexpr int S = 2048;
static constexpr int T = 48;
static constexpr int HALF = S / 2;

typedef unsigned long long u64;

// ---- packed f32x2 helpers (Blackwell FFMA2: only reachable via PTX) ----
__device__ __forceinline__ u64 pack2(float x, float y) {
    u64 r; asm("mov.b64 %0, {%1, %2};" : "=l"(r) : "f"(x), "f"(y)); return r;
}
__device__ __forceinline__ void unpack2(u64 v, float& x, float& y) {
    asm("mov.b64 {%0, %1}, %2;" : "=f"(x), "=f"(y) : "l"(v));
}
__device__ __forceinline__ u64 ffma2(u64 a, u64 b, u64 c) {
    u64 d; asm("fma.rn.f32x2 %0, %1, %2, %3;" : "=l"(d) : "l"(a), "l"(b), "l"(c)); return d;
}
__device__ __forceinline__ u64 fmul2(u64 a, u64 b) {
    u64 d; asm("mul.rn.f32x2 %0, %1, %2;" : "=l"(d) : "l"(a), "l"(b)); return d;
}
__device__ __forceinline__ u64 fadd2(u64 a, u64 b) {
    u64 d; asm("add.rn.f32x2 %0, %1, %2;" : "=l"(d) : "l"(a), "l"(b)); return d;
}

// One scaled-exp-domain semiring chain. BW=0: alpha forward (matvec then *exp(e)).
// BW=1: beta backward (*exp(e) then matvec). Lane l owns states (2l, 2l+1); lanes
// 24..31 are padding (E rows zeroed, Fe forced 0 -> p stays exactly 0).
template<int BW>
__device__ __forceinline__ void run_chain(
    const float* __restrict__ ep0,   // emissions + b*S*T + j0
    const u64 (&E)[48],
    u64 p, int niter, bool act, int lane,
    float4 (*buf)[24],               // per-warp double buffer [2][24]
    u64& pOut, float& cOut)
{
    float c = 0.f;
    float2 ebuf[8];
    int cb = 0;

#define E_OFF(i) ( BW ? (size_t)(S - 1 - (i)) * T : (size_t)((i) + 1) * T )

#pragma unroll
    for (int u = 0; u < 8; ++u)
        if (u < niter) ebuf[u] = *(const float2*)(ep0 + E_OFF(u));

#define BODY(i, u, RENORM) do {                                            \
    float2 e = ebuf[u];                                                    \
    int tn = (i) + 8;                                                      \
    if (tn < niter) ebuf[u] = *(const float2*)(ep0 + E_OFF(tn));           \
    float fex = act ? __expf(e.x) : 0.f;                                   \
    float fey = act ? __expf(e.y) : 0.f;                                   \
    u64 Fe = pack2(fex, fey);                                              \
    u64 src = BW ? fmul2(p, Fe) : p;                                       \
    if (act) {                                                             \
        float sx, sy; unpack2(src, sx, sy);                                \
        buf[cb][lane] = make_float4(sx, sx, sy, sy);                       \
    }                                                                      \
    __syncwarp();                                                          \
    u64 a0 = 0ull, a1 = 0ull, a2 = 0ull, a3 = 0ull;                        \
    _Pragma("unroll")                                                      \
    for (int k = 0; k < 24; k += 2) {                                      \
        float4 v0 = buf[cb][k];                                            \
        a0 = ffma2(E[2*k],   pack2(v0.x, v0.y), a0);                       \
        a1 = ffma2(E[2*k+1], pack2(v0.z, v0.w), a1);                       \
        float4 v1 = buf[cb][k+1];                                          \
        a2 = ffma2(E[2*k+2], pack2(v1.x, v1.y), a2);                       \
        a3 = ffma2(E[2*k+3], pack2(v1.z, v1.w), a3);                       \
    }                                                                      \
    u64 q = fadd2(fadd2(a0, a2), fadd2(a1, a3));                           \
    p = BW ? q : fmul2(q, Fe);                                             \
    cb ^= 1;                                                               \
    if (RENORM) {                                                          \
        float px_, py_; unpack2(p, px_, py_);                              \
        float ref = __shfl_sync(0xffffffffu, px_, 0);                      \
        float inv = __fdividef(1.f, ref);                                  \
        p = fmul2(p, pack2(inv, inv));                                     \
        c += __logf(ref);                                                  \
    }                                                                      \
} while (0)

    int nmain = niter & ~7;
    for (int i = 0; i < nmain; i += 8) {
#pragma unroll
        for (int u = 0; u < 8; ++u) BODY(i + u, u, (u == 3 || u == 7));
    }
#pragma unroll
    for (int u = 0; u < 8; ++u)
        if (nmain + u < niter) BODY(nmain + u, u, false);

    // final renorm so combine products stay well inside fp32 range
    {
        float px_, py_; unpack2(p, px_, py_);
        float ref = __shfl_sync(0xffffffffu, px_, 0);
        float inv = __fdividef(1.f, ref);
        p = fmul2(p, pack2(inv, inv));
        c += __logf(ref);
    }
    pOut = p; cOut = c;
#undef BODY
#undef E_OFF
}

__global__ void __launch_bounds__(64, 2)
crf_kernel(const float* __restrict__ emis,
           const int*   __restrict__ tagsw,   // int32 view; int64 auto-detected
           const int*   __restrict__ mask,
           const float* __restrict__ trans,
           const float* __restrict__ startT,
           const float* __restrict__ endT,
           float* __restrict__ out)
{
    __shared__ float4 bufs[2][2][24];   // [warp][double-buffer][pair]
    __shared__ float shP[48], shR[48], shC[2];
    __shared__ float shRed[64];

    const int b   = blockIdx.x;
    const int tid = threadIdx.x;
    const int w   = tid >> 5;            // warp 0: forward, warp 1: backward
    const int l   = tid & 31;
    const bool act = l < 24;
    const int j0 = act ? 2*l     : 0;
    const int j1 = act ? 2*l + 1 : 0;

    const size_t base = (size_t)b * S * T;

    // per-lane exp(transition) constants in registers (96 regs)
    u64 E[48];
    if (w == 0) {
#pragma unroll
        for (int i = 0; i < 48; ++i) {      // column pairs: E[i][j0], E[i][j1]
            float a  = __expf(trans[i*T + j0]);
            float bb = __expf(trans[i*T + j1]);
            E[i] = act ? pack2(a, bb) : 0ull;
        }
    } else {
#pragma unroll
        for (int j = 0; j < 48; ++j) {      // row pairs: E[j0][j], E[j1][j]
            float a  = __expf(trans[j0*T + j]);
            float bb = __expf(trans[j1*T + j]);
            E[j] = act ? pack2(a, bb) : 0ull;
        }
    }

    const float* ep0 = emis + base + j0;

    u64 pfin; float cfin;
    if (w == 0) {
        float2 e0 = *(const float2*)(ep0);                    // t = 0
        u64 p0 = act ? pack2(__expf(startT[j0] + e0.x),
                             __expf(startT[j1] + e0.y)) : 0ull;
        run_chain<0>(ep0, E, p0, HALF - 1, act, l, bufs[0], pfin, cfin);
    } else {
        u64 p0 = act ? pack2(__expf(endT[j0]), __expf(endT[j1])) : 0ull;
        run_chain<1>(ep0, E, p0, HALF,     act, l, bufs[1], pfin, cfin);
    }

    if (act) {
        float px, py; unpack2(pfin, px, py);
        if (w == 0) { shP[2*l] = px; shP[2*l+1] = py; }
        else        { shR[2*l] = px; shR[2*l+1] = py; }
    }
    if (l == 0) shC[w] = cfin;
    __syncthreads();

    shRed[tid] = (tid < 48) ? shP[tid] * shR[tid] : 0.f;
    __syncthreads();

    float Z = 0.f;
    if (tid == 0) {
        float dot = 0.f;
#pragma unroll
        for (int k = 0; k < 48; ++k) dot += shRed[k];
        Z = __logf(dot) + shC[0] + shC[1];          // log-partition (denominator)
    }

    // ---- tags dtype detection: int64 iff sampled odd 32-bit words all zero ----
    int oddw = tagsw[2*tid + 1];
    int any  = __syncthreads_or(oddw != 0);          // also a barrier for shRed reuse
    const bool is64 = (any == 0);

    // ---- numerator: gold-path score ----
    const size_t tbase = (size_t)b * S;
    float num = 0.f;
#pragma unroll 4
    for (int k = 0; k < 32; ++k) {
        int s = tid + 64*k;
        int cur = is64 ? tagsw[(tbase + s) * 2] : tagsw[tbase + s];
        if (s == 0) {
            num += startT[cur] + emis[base + cur];
        } else {
            int prev = is64 ? tagsw[(tbase + s - 1) * 2] : tagsw[tbase + s - 1];
            float m = (float)mask[tbase + s];
            num += (trans[prev*T + cur] + emis[base + (size_t)s*T + cur]) * m;
        }
        if (s == S - 1) num += endT[cur];
    }
    shRed[tid] = num;
    __syncthreads();
    if (tid == 0) {
        float tot = 0.f;
#pragma unroll
        for (int k = 0; k < 64; ++k) tot += shRed[k];
        out[b] = Z - tot;                            // NLL
    }
}

extern "C" void kernel_launch(void* const* d_in, const int* in_sizes, int n_in,
                              void* d_out, int out_size) {
    (void)in_sizes; (void)n_in; (void)out_size;
    crf_kernel<<<B, 64>>>(
        (const float*)d_in[0],   // emissions
        (const int*)  d_in[1],   // tags (i32 or i64, detected on device)
        (const int*)  d_in[2],   // mask
        (const float*)d_in[3],   // transitions
        (const float*)d_in[4],   // start_transitions
        (const float*)d_in[5],   // end_transitions
        (float*)d_out);
}